// round 2
// baseline (speedup 1.0000x reference)
#include <cuda_runtime.h>
#include <cuda_bf16.h>
#include <math.h>

// Problem constants
#define BATCH 4
#define SEQ   2048
#define NDIM  768
#define HDIM  768
#define MTOT  (BATCH * SEQ)          // 8192

// Scratch (allocation-free: __device__ globals)
__device__ float g_q[MTOT * HDIM];
__device__ float g_k[MTOT * HDIM];
__device__ float g_v[MTOT * HDIM];
__device__ float g_y[MTOT * HDIM];
__device__ float g_s[(long long)BATCH * SEQ * SEQ];   // 67 MB scores

// ---------------------------------------------------------------------------
// Generic fp32 tiled GEMM:
//   C[m,n] = sum_k A[m,k] * Bsel + bias[n]
//   BT=true : B is [N,K] row-major (C = A * B^T)   — projections, QK^T
//   BT=false: B is [K,N] row-major (C = A * B)      — P*V
// Tiles: BM=128 BN=64 BK=16, per-thread 8x4, 256 threads.
// Requires M%128==0, N%64==0, K%16==0 (all shapes here satisfy this).
// ---------------------------------------------------------------------------
template <bool BT>
__global__ void __launch_bounds__(256) sgemm_kernel(
    const float* __restrict__ A, const float* __restrict__ B,
    const float* __restrict__ bias, float* __restrict__ C,
    int M, int N, int K,
    long long strideA, long long strideB, long long strideC)
{
    constexpr int BM = 128, BN = 64, BK = 16, TM = 8, TN = 4;

    A += (long long)blockIdx.z * strideA;
    B += (long long)blockIdx.z * strideB;
    C += (long long)blockIdx.z * strideC;

    __shared__ float As[BK][BM];
    __shared__ float Bs[BK][BN];

    const int tid = threadIdx.x;
    const int bm = blockIdx.y * BM;
    const int bn = blockIdx.x * BN;

    const int tc = tid % (BN / TN);   // 0..15
    const int tr = tid / (BN / TN);   // 0..15

    float acc[TM][TN];
    #pragma unroll
    for (int i = 0; i < TM; i++)
        #pragma unroll
        for (int j = 0; j < TN; j++) acc[i][j] = 0.f;

    // A-tile loader mapping: 512 float4 per tile, 2 per thread
    const int a_m  = tid / (BK / 4);    // 0..63
    const int a_k4 = tid % (BK / 4);    // 0..3

    for (int k0 = 0; k0 < K; k0 += BK) {
        // --- load A tile (BM x BK), stored transposed As[k][m] ---
        #pragma unroll
        for (int r = 0; r < 2; r++) {
            const int m = a_m + r * 64;
            float4 va = *reinterpret_cast<const float4*>(
                A + (long long)(bm + m) * K + k0 + a_k4 * 4);
            As[a_k4 * 4 + 0][m] = va.x;
            As[a_k4 * 4 + 1][m] = va.y;
            As[a_k4 * 4 + 2][m] = va.z;
            As[a_k4 * 4 + 3][m] = va.w;
        }
        // --- load B tile ---
        if (BT) {
            // B is [N,K]; tile BN x BK, store transposed Bs[k][n]
            const int n  = tid / 4;       // 0..63
            const int k4 = tid % 4;
            float4 vb = *reinterpret_cast<const float4*>(
                B + (long long)(bn + n) * K + k0 + k4 * 4);
            Bs[k4 * 4 + 0][n] = vb.x;
            Bs[k4 * 4 + 1][n] = vb.y;
            Bs[k4 * 4 + 2][n] = vb.z;
            Bs[k4 * 4 + 3][n] = vb.w;
        } else {
            // B is [K,N]; tile BK x BN, direct copy
            const int k  = tid / 16;      // 0..15
            const int n4 = tid % 16;      // 0..15
            float4 vb = *reinterpret_cast<const float4*>(
                B + (long long)(k0 + k) * N + bn + n4 * 4);
            *reinterpret_cast<float4*>(&Bs[k][n4 * 4]) = vb;
        }
        __syncthreads();

        #pragma unroll
        for (int kk = 0; kk < BK; kk++) {
            float ra[TM];
            float4 ra0 = *reinterpret_cast<const float4*>(&As[kk][tr * TM]);
            float4 ra1 = *reinterpret_cast<const float4*>(&As[kk][tr * TM + 4]);
            ra[0]=ra0.x; ra[1]=ra0.y; ra[2]=ra0.z; ra[3]=ra0.w;
            ra[4]=ra1.x; ra[5]=ra1.y; ra[6]=ra1.z; ra[7]=ra1.w;
            float4 rb4 = *reinterpret_cast<const float4*>(&Bs[kk][tc * TN]);
            float rb[TN] = {rb4.x, rb4.y, rb4.z, rb4.w};
            #pragma unroll
            for (int i = 0; i < TM; i++)
                #pragma unroll
                for (int j = 0; j < TN; j++)
                    acc[i][j] = fmaf(ra[i], rb[j], acc[i][j]);
        }
        __syncthreads();
    }

    // --- epilogue: optional bias, vectorized store ---
    #pragma unroll
    for (int i = 0; i < TM; i++) {
        const int m = bm + tr * TM + i;
        const int n = bn + tc * TN;
        float4 v;
        v.x = acc[i][0]; v.y = acc[i][1]; v.z = acc[i][2]; v.w = acc[i][3];
        if (bias) {
            v.x += bias[n + 0];
            v.y += bias[n + 1];
            v.z += bias[n + 2];
            v.w += bias[n + 3];
        }
        *reinterpret_cast<float4*>(C + (long long)m * N + n) = v;
    }
}

// ---------------------------------------------------------------------------
// Row softmax over SEQ=2048 columns. One block (256 thr) per row, row cached
// in smem so global traffic is one read + one write.
// ---------------------------------------------------------------------------
__global__ void __launch_bounds__(256) softmax_rows_kernel(float* __restrict__ S)
{
    __shared__ float buf[SEQ];
    __shared__ float red[8];

    const int tid = threadIdx.x;
    float* row = S + (long long)blockIdx.x * SEQ;

    float m = -1e30f;
    #pragma unroll
    for (int i = 0; i < SEQ / 256; i++) {
        float v = row[tid + i * 256];
        buf[tid + i * 256] = v;
        m = fmaxf(m, v);
    }
    #pragma unroll
    for (int o = 16; o > 0; o >>= 1)
        m = fmaxf(m, __shfl_xor_sync(0xffffffffu, m, o));
    if ((tid & 31) == 0) red[tid >> 5] = m;
    __syncthreads();
    float bmax = red[0];
    #pragma unroll
    for (int w = 1; w < 8; w++) bmax = fmaxf(bmax, red[w]);
    __syncthreads();   // red reuse

    float s = 0.f;
    #pragma unroll
    for (int i = 0; i < SEQ / 256; i++) {
        float e = __expf(buf[tid + i * 256] - bmax);
        buf[tid + i * 256] = e;
        s += e;
    }
    #pragma unroll
    for (int o = 16; o > 0; o >>= 1)
        s += __shfl_xor_sync(0xffffffffu, s, o);
    if ((tid & 31) == 0) red[tid >> 5] = s;
    __syncthreads();
    float tot = 0.f;
    #pragma unroll
    for (int w = 0; w < 8; w++) tot += red[w];
    const float inv = 1.f / tot;

    #pragma unroll
    for (int i = 0; i < SEQ / 256; i++)
        row[tid + i * 256] = buf[tid + i * 256] * inv;
}

// ---------------------------------------------------------------------------
extern "C" void kernel_launch(void* const* d_in, const int* in_sizes, int n_in,
                              void* d_out, int out_size)
{
    const float* x  = (const float*)d_in[0];
    const float* wq = (const float*)d_in[1];
    const float* bq = (const float*)d_in[2];
    const float* wk = (const float*)d_in[3];
    const float* bk = (const float*)d_in[4];
    const float* wv = (const float*)d_in[5];
    const float* bv = (const float*)d_in[6];
    const float* wo = (const float*)d_in[7];
    const float* bo = (const float*)d_in[8];
    float* out = (float*)d_out;

    float *q, *k, *v, *y, *s;
    cudaGetSymbolAddress((void**)&q, g_q);
    cudaGetSymbolAddress((void**)&k, g_k);
    cudaGetSymbolAddress((void**)&v, g_v);
    cudaGetSymbolAddress((void**)&y, g_y);
    cudaGetSymbolAddress((void**)&s, g_s);

    const dim3 blk(256);

    // 1) QKV projections: [8192,768] x [768,768]^T + bias
    {
        dim3 grid(HDIM / 64, MTOT / 128, 1);
        sgemm_kernel<true><<<grid, blk>>>(x, wq, bq, q, MTOT, HDIM, NDIM, 0, 0, 0);
        sgemm_kernel<true><<<grid, blk>>>(x, wk, bk, k, MTOT, HDIM, NDIM, 0, 0, 0);
        sgemm_kernel<true><<<grid, blk>>>(x, wv, bv, v, MTOT, HDIM, NDIM, 0, 0, 0);
    }

    // 2) scores[b] = Q_b * K_b^T   (M=N=2048, K=768), batched over z
    {
        dim3 grid(SEQ / 64, SEQ / 128, BATCH);
        sgemm_kernel<true><<<grid, blk>>>(q, k, nullptr, s, SEQ, SEQ, HDIM,
                                          (long long)SEQ * HDIM,
                                          (long long)SEQ * HDIM,
                                          (long long)SEQ * SEQ);
    }

    // 3) row softmax over all BATCH*SEQ rows
    softmax_rows_kernel<<<BATCH * SEQ, 256>>>(s);

    // 4) y[b] = P_b * V_b   (M=2048, N=768, K=2048), B is [K,N]
    {
        dim3 grid(HDIM / 64, SEQ / 128, BATCH);
        sgemm_kernel<false><<<grid, blk>>>(s, v, nullptr, y, SEQ, HDIM, SEQ,
                                           (long long)SEQ * SEQ,
                                           (long long)SEQ * HDIM,
                                           (long long)SEQ * HDIM);
    }

    // 5) out = Y * Wo^T + bo   (M=8192, N=768, K=768)
    {
        dim3 grid(NDIM / 64, MTOT / 128, 1);
        sgemm_kernel<true><<<grid, blk>>>(y, wo, bo, out, MTOT, NDIM, HDIM, 0, 0, 0);
    }
}

// round 3
// speedup vs baseline: 2.3126x; 2.3126x over previous
#include <cuda_runtime.h>
#include <cuda_bf16.h>
#include <stdint.h>
#include <math.h>

#define BATCH 4
#define SEQ   2048
#define NDIM  768
#define HDIM  768
#define MTOT  (BATCH * SEQ)

// Scratch (allocation-free)
__device__ float g_q[MTOT * HDIM];
__device__ float g_k[MTOT * HDIM];
__device__ float g_v[MTOT * HDIM];
__device__ float g_y[MTOT * HDIM];
__device__ float g_s[(long long)BATCH * SEQ * SEQ];

// smem strides (uint32 words), padded for conflict-free fragment loads
#define ASTRIDE 20    // A: 16 k-pairs per row + 4 pad  -> banks (20r+c)%32 all-distinct
#define BSTRIDE 136   // B: 128 n per k2-row + 8 pad    -> banks (8k2+n)%32 all-distinct

__device__ __forceinline__ void mma16816(float* d, const uint32_t* a, const uint32_t* b)
{
    asm volatile(
        "mma.sync.aligned.m16n8k16.row.col.f32.bf16.bf16.f32 "
        "{%0,%1,%2,%3},{%4,%5,%6,%7},{%8,%9},{%0,%1,%2,%3};\n"
        : "+f"(d[0]), "+f"(d[1]), "+f"(d[2]), "+f"(d[3])
        : "r"(a[0]), "r"(a[1]), "r"(a[2]), "r"(a[3]), "r"(b[0]), "r"(b[1]));
}

// Split two fp32 values into packed (hi,hi) and (lo,lo) bf16x2 words.
// x = hi + lo with |lo rounding| ~ 2^-18 * |x|  -> near-fp32 GEMM accuracy.
__device__ __forceinline__ void split_pair(float x0, float x1, uint32_t& hi, uint32_t& lo)
{
    __nv_bfloat16 h0 = __float2bfloat16(x0);
    __nv_bfloat16 h1 = __float2bfloat16(x1);
    float r0 = x0 - __bfloat162float(h0);
    float r1 = x1 - __bfloat162float(h1);
    __nv_bfloat16 l0 = __float2bfloat16(r0);
    __nv_bfloat16 l1 = __float2bfloat16(r1);
    __nv_bfloat162 hv = __halves2bfloat162(h0, h1);
    __nv_bfloat162 lv = __halves2bfloat162(l0, l1);
    hi = *reinterpret_cast<uint32_t*>(&hv);
    lo = *reinterpret_cast<uint32_t*>(&lv);
}

// ---------------------------------------------------------------------------
// Tensor-core GEMM, split-bf16 (3 MMA per logical MMA), fp32 I/O.
//   BT=true : B is [N,K] row-major  => C = A * B^T   (projections, QK^T)
//   BT=false: B is [K,N] row-major  => C = A * B     (P*V)
// Block tile 128x128, BK=32, 8 warps of 64x32. Requires M%128==0, N%128==0,
// K%32==0 (all shapes here comply).
// ---------------------------------------------------------------------------
template <bool BT>
__global__ void __launch_bounds__(256) tc_gemm(
    const float* __restrict__ A, const float* __restrict__ B,
    const float* __restrict__ bias, float* __restrict__ C,
    int M, int N, int K,
    long long sA, long long sB, long long sC)
{
    __shared__ uint32_t AsH[128 * ASTRIDE];
    __shared__ uint32_t AsL[128 * ASTRIDE];
    __shared__ uint32_t BsH[16 * BSTRIDE];
    __shared__ uint32_t BsL[16 * BSTRIDE];

    A += (long long)blockIdx.z * sA;
    B += (long long)blockIdx.z * sB;
    C += (long long)blockIdx.z * sC;

    const int tid  = threadIdx.x;
    const int lane = tid & 31;
    const int warp = tid >> 5;
    const int bm = blockIdx.y * 128;
    const int bn = blockIdx.x * 128;
    const int wm = (warp & 1) * 64;    // warp-tile m origin
    const int wn = (warp >> 1) * 32;   // warp-tile n origin
    const int r = lane >> 2;           // 0..7
    const int c = lane & 3;            // 0..3

    float acc[4][4][4];
    #pragma unroll
    for (int i = 0; i < 4; i++)
        #pragma unroll
        for (int j = 0; j < 4; j++)
            #pragma unroll
            for (int e = 0; e < 4; e++) acc[i][j][e] = 0.f;

    // --- loader index precompute ---
    // A (and BT=true B) tiles: [128 rows][32 k] fp32, thread j-th float4:
    //   row = tid/8 + 32j, k4 = tid%8  (fully coalesced 128B per warp)
    const int a_m0 = tid >> 3;
    const int a_k4 = tid & 7;
    const float* Aptr = A + (long long)(bm + a_m0) * K + a_k4 * 4;
    const float* Bt_ptr = B + (long long)(bn + a_m0) * K + a_k4 * 4;   // BT=true
    // BT=false tiles: [32 k][128 n], thread handles k2 = tid/32 + 8i, n4 = tid%32
    const int b_k2 = tid >> 5;
    const int b_n4 = tid & 31;
    const float* Bf_ptr = B + (long long)(2 * b_k2) * N + bn + b_n4 * 4; // BT=false

    float4 ra[4];
    float4 rb[4];

    // prologue: load tile 0
    {
        #pragma unroll
        for (int j = 0; j < 4; j++)
            ra[j] = *reinterpret_cast<const float4*>(Aptr + (long long)32 * j * K);
        if (BT) {
            #pragma unroll
            for (int j = 0; j < 4; j++)
                rb[j] = *reinterpret_cast<const float4*>(Bt_ptr + (long long)32 * j * K);
        } else {
            #pragma unroll
            for (int i = 0; i < 2; i++) {
                const float* p = Bf_ptr + (long long)16 * i * N;
                rb[2 * i + 0] = *reinterpret_cast<const float4*>(p);
                rb[2 * i + 1] = *reinterpret_cast<const float4*>(p + N);
            }
        }
    }

    const int T = K / 32;
    for (int t = 0; t < T; t++) {
        // --- convert + store stage regs into smem ---
        #pragma unroll
        for (int j = 0; j < 4; j++) {
            const int m = a_m0 + 32 * j;
            const int base = m * ASTRIDE + 2 * a_k4;
            split_pair(ra[j].x, ra[j].y, AsH[base],     AsL[base]);
            split_pair(ra[j].z, ra[j].w, AsH[base + 1], AsL[base + 1]);
        }
        if (BT) {
            #pragma unroll
            for (int j = 0; j < 4; j++) {
                const int n = a_m0 + 32 * j;
                split_pair(rb[j].x, rb[j].y, BsH[(2 * a_k4) * BSTRIDE + n],
                                             BsL[(2 * a_k4) * BSTRIDE + n]);
                split_pair(rb[j].z, rb[j].w, BsH[(2 * a_k4 + 1) * BSTRIDE + n],
                                             BsL[(2 * a_k4 + 1) * BSTRIDE + n]);
            }
        } else {
            #pragma unroll
            for (int i = 0; i < 2; i++) {
                const int k2 = b_k2 + 8 * i;
                const float4 f0 = rb[2 * i + 0];
                const float4 f1 = rb[2 * i + 1];
                const int base = k2 * BSTRIDE + 4 * b_n4;
                split_pair(f0.x, f1.x, BsH[base + 0], BsL[base + 0]);
                split_pair(f0.y, f1.y, BsH[base + 1], BsL[base + 1]);
                split_pair(f0.z, f1.z, BsH[base + 2], BsL[base + 2]);
                split_pair(f0.w, f1.w, BsH[base + 3], BsL[base + 3]);
            }
        }
        __syncthreads();

        // --- issue global loads for next tile (overlap with compute) ---
        if (t + 1 < T) {
            const int k0 = (t + 1) * 32;
            #pragma unroll
            for (int j = 0; j < 4; j++)
                ra[j] = *reinterpret_cast<const float4*>(Aptr + (long long)32 * j * K + k0);
            if (BT) {
                #pragma unroll
                for (int j = 0; j < 4; j++)
                    rb[j] = *reinterpret_cast<const float4*>(Bt_ptr + (long long)32 * j * K + k0);
            } else {
                #pragma unroll
                for (int i = 0; i < 2; i++) {
                    const float* p = Bf_ptr + (long long)(k0 + 16 * i) * N;
                    rb[2 * i + 0] = *reinterpret_cast<const float4*>(p);
                    rb[2 * i + 1] = *reinterpret_cast<const float4*>(p + N);
                }
            }
        }

        // --- compute: 2 k-steps of m16n8k16, 3 MMAs each (hi*hi, hi*lo, lo*hi) ---
        #pragma unroll
        for (int ks = 0; ks < 2; ks++) {
            uint32_t aH[4][4], aL[4][4], bH[4][2], bL[4][2];
            #pragma unroll
            for (int mi = 0; mi < 4; mi++) {
                const int row = wm + mi * 16 + r;
                const int col = 8 * ks + c;
                aH[mi][0] = AsH[row * ASTRIDE + col];
                aH[mi][1] = AsH[(row + 8) * ASTRIDE + col];
                aH[mi][2] = AsH[row * ASTRIDE + col + 4];
                aH[mi][3] = AsH[(row + 8) * ASTRIDE + col + 4];
                aL[mi][0] = AsL[row * ASTRIDE + col];
                aL[mi][1] = AsL[(row + 8) * ASTRIDE + col];
                aL[mi][2] = AsL[row * ASTRIDE + col + 4];
                aL[mi][3] = AsL[(row + 8) * ASTRIDE + col + 4];
            }
            #pragma unroll
            for (int ni = 0; ni < 4; ni++) {
                const int n = wn + ni * 8 + r;
                const int k2a = 8 * ks + c;
                bH[ni][0] = BsH[k2a * BSTRIDE + n];
                bH[ni][1] = BsH[(k2a + 4) * BSTRIDE + n];
                bL[ni][0] = BsL[k2a * BSTRIDE + n];
                bL[ni][1] = BsL[(k2a + 4) * BSTRIDE + n];
            }
            #pragma unroll
            for (int mi = 0; mi < 4; mi++)
                #pragma unroll
                for (int ni = 0; ni < 4; ni++) {
                    mma16816(acc[mi][ni], aH[mi], bH[ni]);
                    mma16816(acc[mi][ni], aH[mi], bL[ni]);
                    mma16816(acc[mi][ni], aL[mi], bH[ni]);
                }
        }
        __syncthreads();
    }

    // --- epilogue ---
    #pragma unroll
    for (int mi = 0; mi < 4; mi++)
        #pragma unroll
        for (int ni = 0; ni < 4; ni++) {
            const int row = bm + wm + mi * 16 + r;
            const int col = bn + wn + ni * 8 + 2 * c;
            float2 v0 = make_float2(acc[mi][ni][0], acc[mi][ni][1]);
            float2 v1 = make_float2(acc[mi][ni][2], acc[mi][ni][3]);
            if (bias) {
                const float b0 = bias[col], b1 = bias[col + 1];
                v0.x += b0; v0.y += b1;
                v1.x += b0; v1.y += b1;
            }
            *reinterpret_cast<float2*>(C + (long long)row * N + col) = v0;
            *reinterpret_cast<float2*>(C + (long long)(row + 8) * N + col) = v1;
        }
}

// ---------------------------------------------------------------------------
// Row softmax over SEQ=2048 columns (one 256-thread block per row).
// ---------------------------------------------------------------------------
__global__ void __launch_bounds__(256) softmax_rows_kernel(float* __restrict__ S)
{
    __shared__ float buf[SEQ];
    __shared__ float red[8];

    const int tid = threadIdx.x;
    float* row = S + (long long)blockIdx.x * SEQ;

    float m = -1e30f;
    #pragma unroll
    for (int i = 0; i < SEQ / 256; i++) {
        float v = row[tid + i * 256];
        buf[tid + i * 256] = v;
        m = fmaxf(m, v);
    }
    #pragma unroll
    for (int o = 16; o > 0; o >>= 1)
        m = fmaxf(m, __shfl_xor_sync(0xffffffffu, m, o));
    if ((tid & 31) == 0) red[tid >> 5] = m;
    __syncthreads();
    float bmax = red[0];
    #pragma unroll
    for (int w = 1; w < 8; w++) bmax = fmaxf(bmax, red[w]);
    __syncthreads();

    float s = 0.f;
    #pragma unroll
    for (int i = 0; i < SEQ / 256; i++) {
        float e = __expf(buf[tid + i * 256] - bmax);
        buf[tid + i * 256] = e;
        s += e;
    }
    #pragma unroll
    for (int o = 16; o > 0; o >>= 1)
        s += __shfl_xor_sync(0xffffffffu, s, o);
    if ((tid & 31) == 0) red[tid >> 5] = s;
    __syncthreads();
    float tot = 0.f;
    #pragma unroll
    for (int w = 0; w < 8; w++) tot += red[w];
    const float inv = 1.f / tot;

    #pragma unroll
    for (int i = 0; i < SEQ / 256; i++)
        row[tid + i * 256] = buf[tid + i * 256] * inv;
}

// ---------------------------------------------------------------------------
extern "C" void kernel_launch(void* const* d_in, const int* in_sizes, int n_in,
                              void* d_out, int out_size)
{
    const float* x  = (const float*)d_in[0];
    const float* wq = (const float*)d_in[1];
    const float* bq = (const float*)d_in[2];
    const float* wk = (const float*)d_in[3];
    const float* bk = (const float*)d_in[4];
    const float* wv = (const float*)d_in[5];
    const float* bv = (const float*)d_in[6];
    const float* wo = (const float*)d_in[7];
    const float* bo = (const float*)d_in[8];
    float* out = (float*)d_out;

    float *q, *k, *v, *y, *s;
    cudaGetSymbolAddress((void**)&q, g_q);
    cudaGetSymbolAddress((void**)&k, g_k);
    cudaGetSymbolAddress((void**)&v, g_v);
    cudaGetSymbolAddress((void**)&y, g_y);
    cudaGetSymbolAddress((void**)&s, g_s);

    const dim3 blk(256);

    // 1) QKV projections: [8192,768] x [768,768]^T + bias
    {
        dim3 grid(HDIM / 128, MTOT / 128, 1);
        tc_gemm<true><<<grid, blk>>>(x, wq, bq, q, MTOT, HDIM, NDIM, 0, 0, 0);
        tc_gemm<true><<<grid, blk>>>(x, wk, bk, k, MTOT, HDIM, NDIM, 0, 0, 0);
        tc_gemm<true><<<grid, blk>>>(x, wv, bv, v, MTOT, HDIM, NDIM, 0, 0, 0);
    }

    // 2) scores[b] = Q_b * K_b^T   (M=N=2048, K=768)
    {
        dim3 grid(SEQ / 128, SEQ / 128, BATCH);
        tc_gemm<true><<<grid, blk>>>(q, k, nullptr, s, SEQ, SEQ, HDIM,
                                     (long long)SEQ * HDIM,
                                     (long long)SEQ * HDIM,
                                     (long long)SEQ * SEQ);
    }

    // 3) row softmax
    softmax_rows_kernel<<<BATCH * SEQ, 256>>>(s);

    // 4) y[b] = P_b * V_b   (M=2048, N=768, K=2048), B is [K,N]
    {
        dim3 grid(HDIM / 128, SEQ / 128, BATCH);
        tc_gemm<false><<<grid, blk>>>(s, v, nullptr, y, SEQ, HDIM, SEQ,
                                      (long long)SEQ * SEQ,
                                      (long long)SEQ * HDIM,
                                      (long long)SEQ * HDIM);
    }

    // 5) out = Y * Wo^T + bo   (M=8192, N=768, K=768)
    {
        dim3 grid(NDIM / 128, MTOT / 128, 1);
        tc_gemm<true><<<grid, blk>>>(y, wo, bo, out, MTOT, NDIM, HDIM, 0, 0, 0);
    }
}